// round 2
// baseline (speedup 1.0000x reference)
#include <cuda_runtime.h>

// Problem constants
#define GRID   128
#define BLOCK  256
#define Bsz    256
#define Tsz    512
#define Hsz    512
#define NPOS   128
#define NACT   64
#define Isz    192          // NPOS + NACT
#define Ktot   704          // Isz + Hsz
#define KT     32           // K-tile
#define NTILES 22           // 704/32
#define XTILES 6            // tiles 0..5 come from x, 6..21 from h

// h ping-pong buffers, layout [H][B] (unit-major) so step loads are coalesced copies
__device__ float g_h[2][Hsz * Bsz];
__device__ volatile unsigned g_bar;

__global__ void reset_kernel() { g_bar = 0u; }

__device__ __forceinline__ float sigf(float x) { return 1.0f / (1.0f + __expf(-x)); }

__device__ __forceinline__ void load_tile(float4* pre, int kt, int t,
                                          const float* __restrict__ obs,
                                          const float* __restrict__ act,
                                          const float* __restrict__ hread,
                                          bool h_gather, int tid)
{
    if (kt < 4) {                       // obs: thread owns batch=tid, 32 contiguous k
        const float4* src = (const float4*)(obs + ((size_t)tid * Tsz + t) * NPOS + kt * KT);
#pragma unroll
        for (int r = 0; r < 8; ++r) pre[r] = src[r];
    } else if (kt < XTILES) {           // act
        const float4* src = (const float4*)(act + ((size_t)tid * Tsz + t) * NACT + (kt - 4) * KT);
#pragma unroll
        for (int r = 0; r < 8; ++r) pre[r] = src[r];
    } else if (h_gather) {              // t==0: h0 is [B][H], gather per batch
        const float4* src = (const float4*)(hread + (size_t)tid * Hsz + (kt - XTILES) * KT);
#pragma unroll
        for (int r = 0; r < 8; ++r) pre[r] = src[r];
    } else {                            // h buffer [H][B]: straight block copy, L2-coherent loads
        const float4* src = (const float4*)(hread + (size_t)(kt - XTILES) * KT * Bsz);
#pragma unroll
        for (int r = 0; r < 8; ++r) pre[r] = __ldcg(src + tid + BLOCK * r);
    }
}

__device__ __forceinline__ void store_tile(const float4* pre, int kt, bool h_gather,
                                           float* Zt, int tid)
{
    bool gathered = (kt < XTILES) || h_gather;
    if (gathered) {                     // transpose: pre[r] holds 4 consecutive k for batch=tid
#pragma unroll
        for (int r = 0; r < 8; ++r) {
            Zt[(r * 4 + 0) * Bsz + tid] = pre[r].x;
            Zt[(r * 4 + 1) * Bsz + tid] = pre[r].y;
            Zt[(r * 4 + 2) * Bsz + tid] = pre[r].z;
            Zt[(r * 4 + 3) * Bsz + tid] = pre[r].w;
        }
    } else {                            // already [k][b]: vector copy
        float4* dst = (float4*)Zt;
#pragma unroll
        for (int r = 0; r < 8; ++r) dst[tid + BLOCK * r] = pre[r];
    }
}

__global__ void __launch_bounds__(BLOCK, 1) lstm_kernel(
    const float* __restrict__ obs, const float* __restrict__ act,
    const float* __restrict__ h0,  const float* __restrict__ c0,
    const float* __restrict__ W_ih, const float* __restrict__ W_hh,
    const float* __restrict__ b_ih, const float* __restrict__ b_hh,
    const float* __restrict__ W_out, const float* __restrict__ b_out,
    float* __restrict__ out)
{
    extern __shared__ float sm[];
    float* Wsm  = sm;                       // [704][16]  (k-major; 16 = unit*4 + gate)
    float* Zt   = Wsm + Ktot * 16;          // [32][256]  current K-tile of [x_t | h]
    float* csm  = Zt + KT * Bsz;            // [4][256]   cell state for my 4 units
    float* wout = csm + 4 * Bsz;            // [512]
    float* bsm  = wout + Hsz;               // [16]       b_ih + b_hh for my 16 gate rows
    float* red  = bsm + 16;                 // [8]        reduction scratch

    const int tid = threadIdx.x;
    const int cta = blockIdx.x;
    const int u   = tid >> 6;               // unit within CTA (0..3)
    const int b0  = (tid & 63) << 2;        // batch base (0..252, step 4)
    const int j   = cta * 4 + u;            // global hidden unit

    // ---- one-time init ----
    for (int idx = tid; idx < Ktot * 16; idx += BLOCK) {
        int k = idx >> 4, col = idx & 15;
        int uu = col >> 2, g = col & 3;
        int row = g * Hsz + cta * 4 + uu;
        Wsm[idx] = (k < Isz) ? W_ih[(size_t)row * Isz + k]
                             : W_hh[(size_t)row * Hsz + (k - Isz)];
    }
    for (int idx = tid; idx < 4 * Bsz; idx += BLOCK) {
        int uu = idx >> 8, b = idx & 255;
        csm[idx] = c0[(size_t)b * Hsz + cta * 4 + uu];
    }
    for (int idx = tid; idx < Hsz; idx += BLOCK) wout[idx] = W_out[idx];
    if (tid < 16) {
        int uu = tid >> 2, g = tid & 3;
        int row = g * Hsz + cta * 4 + uu;
        bsm[tid] = b_ih[row] + b_hh[row];
    }
    __syncthreads();

    float bi[4];
#pragma unroll
    for (int g = 0; g < 4; ++g) bi[g] = bsm[u * 4 + g];

    const float bout = b_out[0];
    unsigned barTarget = GRID;
    float4 pre[8];

    for (int t = 0; t < Tsz; ++t) {
        const bool  hg     = (t == 0);
        const float* hread = hg ? h0 : g_h[(t - 1) & 1];
        float*       hwrite = g_h[t & 1];

        float acc[4][4];
#pragma unroll
        for (int bb = 0; bb < 4; ++bb)
#pragma unroll
            for (int g = 0; g < 4; ++g) acc[bb][g] = bi[g];

        load_tile(pre, 0, t, obs, act, hread, hg, tid);

        for (int kt = 0; kt < NTILES; ++kt) {
            __syncthreads();                        // Zt free (prev compute done)
            store_tile(pre, kt, hg, Zt, tid);
            __syncthreads();                        // tile visible
            if (kt + 1 < NTILES) load_tile(pre, kt + 1, t, obs, act, hread, hg, tid);

            const float* wp = Wsm + (size_t)kt * KT * 16 + u * 4;
#pragma unroll
            for (int k = 0; k < KT; ++k) {
                float4 wv = *(const float4*)(wp + k * 16);          // broadcast
                float4 zb = *(const float4*)(Zt + k * Bsz + b0);    // 4 batches
                acc[0][0] += zb.x * wv.x; acc[0][1] += zb.x * wv.y;
                acc[0][2] += zb.x * wv.z; acc[0][3] += zb.x * wv.w;
                acc[1][0] += zb.y * wv.x; acc[1][1] += zb.y * wv.y;
                acc[1][2] += zb.y * wv.z; acc[1][3] += zb.y * wv.w;
                acc[2][0] += zb.z * wv.x; acc[2][1] += zb.z * wv.y;
                acc[2][2] += zb.z * wv.z; acc[2][3] += zb.z * wv.w;
                acc[3][0] += zb.w * wv.x; acc[3][1] += zb.w * wv.y;
                acc[3][2] += zb.w * wv.z; acc[3][3] += zb.w * wv.w;
            }
        }

        // ---- elementwise LSTM cell update (all in registers + smem c) ----
        float hn[4];
#pragma unroll
        for (int bb = 0; bb < 4; ++bb) {
            float iv = sigf(acc[bb][0]);
            float fv = sigf(acc[bb][1]);
            float gv = tanhf(acc[bb][2]);
            float ov = sigf(acc[bb][3]);
            float cold = csm[u * Bsz + b0 + bb];
            float cn = fv * cold + iv * gv;
            csm[u * Bsz + b0 + bb] = cn;
            hn[bb] = ov * tanhf(cn);
        }
        *(float4*)(hwrite + (size_t)j * Bsz + b0) = make_float4(hn[0], hn[1], hn[2], hn[3]);

        // ---- grid-wide barrier (release/acquire) ----
        __syncthreads();
        if (tid == 0) {
            __threadfence();
            atomicAdd((unsigned*)&g_bar, 1u);
            while (g_bar < barTarget) { }
            __threadfence();
        }
        __syncthreads();
        barTarget += GRID;

        // ---- readout for this step: CTA c owns batches 2c, 2c+1 ----
        {
            const float* hc = hwrite;   // complete after barrier
#pragma unroll
            for (int bb = 0; bb < 2; ++bb) {
                int b = cta * 2 + bb;
                float p = __ldcg(hc + (size_t)tid * Bsz + b) * wout[tid]
                        + __ldcg(hc + ((size_t)tid + 256) * Bsz + b) * wout[tid + 256];
#pragma unroll
                for (int off = 16; off; off >>= 1)
                    p += __shfl_down_sync(0xffffffffu, p, off);
                if ((tid & 31) == 0) red[tid >> 5] = p;
                __syncthreads();
                if (tid == 0) {
                    float s = red[0] + red[1] + red[2] + red[3]
                            + red[4] + red[5] + red[6] + red[7] + bout;
                    out[(size_t)b * Tsz + t] = s;
                }
                __syncthreads();
            }
        }
    }
}

extern "C" void kernel_launch(void* const* d_in, const int* in_sizes, int n_in,
                              void* d_out, int out_size)
{
    (void)in_sizes; (void)n_in; (void)out_size;
    const size_t smem_bytes =
        (size_t)(Ktot * 16 + KT * Bsz + 4 * Bsz + Hsz + 16 + 8) * sizeof(float); // ~84 KB
    cudaFuncSetAttribute(lstm_kernel, cudaFuncAttributeMaxDynamicSharedMemorySize,
                         (int)smem_bytes);

    reset_kernel<<<1, 1>>>();
    lstm_kernel<<<GRID, BLOCK, smem_bytes>>>(
        (const float*)d_in[0],  // observation
        (const float*)d_in[1],  // action
        (const float*)d_in[2],  // h0
        (const float*)d_in[3],  // c0
        (const float*)d_in[4],  // W_ih
        (const float*)d_in[5],  // W_hh
        (const float*)d_in[6],  // b_ih
        (const float*)d_in[7],  // b_hh
        (const float*)d_in[8],  // W_out
        (const float*)d_in[9],  // b_out
        (float*)d_out);
}

// round 4
// speedup vs baseline: 2.4892x; 2.4892x over previous
#include <cuda_runtime.h>
#include <cuda_bf16.h>
#include <cstdint>

#define NMB 4
#define NMU 32
#define GRIDSZ 128
#define BLOCK 256
#define Tsz 512
#define Hsz 512
#define NPOS 128
#define NACT 64

#define WPAD 712          // W smem k-stride (conflict-free frag loads)
#define ZPAD 40           // Z smem k-stride
#define SPAD 68           // stage col-stride
#define NBLK 22           // 704 / 32
#define XBLK 6            // blocks 0..5 from x, 6..21 from h

// shared memory layout (bytes)
#define OFF_WH   0
#define OFF_WL   (OFF_WH + 64*WPAD*2)        // 91136
#define OFF_ZH   (OFF_WL + 64*WPAD*2)        // 182272
#define OFF_ZL   (OFF_ZH + 64*ZPAD*2)        // 187392
#define OFF_ST   (OFF_ZL + 64*ZPAD*2)        // 192512
#define OFF_C    (OFF_ST + 64*SPAD*4)        // 209920
#define OFF_BIAS (OFF_C + 16*64*4)           // 214016
#define OFF_WOUT (OFF_BIAS + 64*4)           // 214272
#define OFF_PRED (OFF_WOUT + 16*4)           // 214336
#define SMEM_TOTAL (OFF_PRED + 256*4)        // 215360

// global ping-pong h image (bf16 hi/lo planes), k = hidden unit 0..511
__device__ unsigned short g_Zhi[2][256][512];
__device__ unsigned short g_Zlo[2][256][512];
__device__ float g_pout[2][NMU][NMB][64];
__device__ volatile unsigned g_bar[NMB];

__global__ void reset_kernel(){ if (threadIdx.x < NMB) g_bar[threadIdx.x] = 0u; }

__device__ __forceinline__ void split2(float v, unsigned short& h, unsigned short& l){
    __nv_bfloat16 hb = __float2bfloat16(v);
    __nv_bfloat16 lb = __float2bfloat16(v - __bfloat162float(hb));
    h = __bfloat16_as_ushort(hb); l = __bfloat16_as_ushort(lb);
}
__device__ __forceinline__ float sigf(float x){ return __fdividef(1.0f, 1.0f + __expf(-x)); }

__device__ __forceinline__ void mma16816(float* d, const unsigned* a, const unsigned* b){
    asm volatile("mma.sync.aligned.m16n8k16.row.col.f32.bf16.bf16.f32 "
        "{%0,%1,%2,%3}, {%4,%5,%6,%7}, {%8,%9}, {%0,%1,%2,%3};"
        : "+f"(d[0]), "+f"(d[1]), "+f"(d[2]), "+f"(d[3])
        : "r"(a[0]), "r"(a[1]), "r"(a[2]), "r"(a[3]), "r"(b[0]), "r"(b[1]));
}

// h0 [B][512] fp32 -> slot 1 bf16 hi/lo image
__global__ void prep_h0_kernel(const float* __restrict__ h0){
    int b = blockIdx.x;
    int j = threadIdx.x * 4;
#pragma unroll
    for (int e = 0; e < 4; ++e) {
        unsigned short h, l; split2(h0[(size_t)b*Hsz + j + e], h, l);
        g_Zhi[1][b][j + e] = h;
        g_Zlo[1][b][j + e] = l;
    }
}

__global__ void __launch_bounds__(BLOCK, 1) lstm_hmma_kernel(
    const float* __restrict__ obs, const float* __restrict__ act,
    const float* __restrict__ h0,  const float* __restrict__ c0,
    const float* __restrict__ W_ih, const float* __restrict__ W_hh,
    const float* __restrict__ b_ih, const float* __restrict__ b_hh,
    const float* __restrict__ W_out, const float* __restrict__ b_out,
    float* __restrict__ out)
{
    extern __shared__ unsigned char sm8[];
    unsigned short* WH = (unsigned short*)(sm8 + OFF_WH);
    unsigned short* WL = (unsigned short*)(sm8 + OFF_WL);
    unsigned short* ZH = (unsigned short*)(sm8 + OFF_ZH);
    unsigned short* ZL = (unsigned short*)(sm8 + OFF_ZL);
    float* stg  = (float*)(sm8 + OFF_ST);
    float* csm  = (float*)(sm8 + OFF_C);
    float* bias = (float*)(sm8 + OFF_BIAS);
    float* wout = (float*)(sm8 + OFF_WOUT);
    float* pred = (float*)(sm8 + OFF_PRED);

    const int tid = threadIdx.x;
    const int wid = tid >> 5, lane = tid & 31, grp = lane >> 2, qid = lane & 3;
    const int mu = blockIdx.x >> 2, mb = blockIdx.x & 3;
    const int kh = wid >> 2;            // split-K half
    const int mh = (wid >> 1) & 1;      // M half (32 rows)
    const int nh = wid & 1;             // N half (32 cols)

    // ---- one-time init: W (bf16 hi/lo split), c, bias, wout ----
    {
        const int r = tid >> 2, l4 = tid & 3;   // row 0..63, 4 threads/row
        const int ul = r >> 2, g = r & 3;
        const int R = g * Hsz + mu * 16 + ul;   // global gate row
        for (int k = l4; k < 704; k += 4) {
            float v = (k < 192) ? W_ih[(size_t)R * 192 + k]
                                : W_hh[(size_t)R * Hsz + (k - 192)];
            unsigned short h, l; split2(v, h, l);
            WH[r * WPAD + k] = h;
            WL[r * WPAD + k] = l;
        }
    }
    for (int i = tid; i < 16 * 64; i += BLOCK) {
        int u = i >> 6, b = i & 63;
        csm[u * 64 + b] = c0[(size_t)(mb * 64 + b) * Hsz + mu * 16 + u];
    }
    if (tid < 64) {
        int R = (tid & 3) * Hsz + mu * 16 + (tid >> 2);
        bias[tid] = b_ih[R] + b_hh[R];
    }
    if (tid < 16) wout[tid] = W_out[mu * 16 + tid];
    __syncthreads();

    const float bout = b_out[0];
    unsigned barTarget = NMU;

    const int zn = tid >> 2;       // Z dest row (batch within group)
    const int zg = tid & 3;        // 16B granule (8 elems)
    const int bg = mb * 64 + zn;   // global batch

    for (int t = 0; t < Tsz; ++t) {
        const int slotR = (t + 1) & 1, slotW = t & 1;
        const float* obsrow = obs + ((size_t)bg * Tsz + t) * NPOS;
        const float* actrow = act + ((size_t)bg * Tsz + t) * NACT;

        float acc[2][4][4];
#pragma unroll
        for (int mt = 0; mt < 2; ++mt)
#pragma unroll
            for (int nt = 0; nt < 4; ++nt)
#pragma unroll
                for (int j = 0; j < 4; ++j) acc[mt][nt][j] = 0.f;

        float4 pf0, pf1; uint4 preH, preL;
        // prefetch block 0 (x)
        {
            const float* s = obsrow + zg * 8;
            pf0 = *(const float4*)s; pf1 = *(const float4*)(s + 4);
        }

        for (int blk = 0; blk < NBLK; ++blk) {
            __syncthreads();   // Z buffer free
            // stage current block into Z smem
            {
                unsigned short* dh = ZH + zn * ZPAD + zg * 8;
                unsigned short* dl = ZL + zn * ZPAD + zg * 8;
                if (blk < XBLK) {
                    float f[8] = {pf0.x, pf0.y, pf0.z, pf0.w, pf1.x, pf1.y, pf1.z, pf1.w};
                    union { unsigned short s[8]; uint4 v; } uh, ul2;
#pragma unroll
                    for (int j = 0; j < 8; ++j) split2(f[j], uh.s[j], ul2.s[j]);
                    *(uint4*)dh = uh.v;
                    *(uint4*)dl = ul2.v;
                } else {
                    *(uint4*)dh = preH;
                    *(uint4*)dl = preL;
                }
            }
            __syncthreads();   // tile visible
            // prefetch next block
            if (blk + 1 < NBLK) {
                const int nb = blk + 1;
                if (nb < XBLK) {
                    const float* s = (nb < 4) ? (obsrow + nb * 32 + zg * 8)
                                              : (actrow + (nb - 4) * 32 + zg * 8);
                    pf0 = *(const float4*)s; pf1 = *(const float4*)(s + 4);
                } else {
                    const int kk = (nb - XBLK) * 32 + zg * 8;
                    preH = __ldcg((const uint4*)&g_Zhi[slotR][bg][kk]);
                    preL = __ldcg((const uint4*)&g_Zlo[slotR][bg][kk]);
                }
            }
            // MMA over this 32-k block (this warp's 16-k half)
            {
                const int kw = blk * 32 + kh * 16 + qid * 2;   // W k index
                const int kz = kh * 16 + qid * 2;              // Z k index
                unsigned aH[2][4], aL[2][4], bH[4][2], bL[4][2];
#pragma unroll
                for (int mt = 0; mt < 2; ++mt) {
                    const int r0 = (mh * 32 + mt * 16 + grp) * WPAD;
                    aH[mt][0] = *(const unsigned*)&WH[r0 + kw];
                    aH[mt][1] = *(const unsigned*)&WH[r0 + 8 * WPAD + kw];
                    aH[mt][2] = *(const unsigned*)&WH[r0 + kw + 8];
                    aH[mt][3] = *(const unsigned*)&WH[r0 + 8 * WPAD + kw + 8];
                    aL[mt][0] = *(const unsigned*)&WL[r0 + kw];
                    aL[mt][1] = *(const unsigned*)&WL[r0 + 8 * WPAD + kw];
                    aL[mt][2] = *(const unsigned*)&WL[r0 + kw + 8];
                    aL[mt][3] = *(const unsigned*)&WL[r0 + 8 * WPAD + kw + 8];
                }
#pragma unroll
                for (int nt = 0; nt < 4; ++nt) {
                    const int n0 = (nh * 32 + nt * 8 + grp) * ZPAD;
                    bH[nt][0] = *(const unsigned*)&ZH[n0 + kz];
                    bH[nt][1] = *(const unsigned*)&ZH[n0 + kz + 8];
                    bL[nt][0] = *(const unsigned*)&ZL[n0 + kz];
                    bL[nt][1] = *(const unsigned*)&ZL[n0 + kz + 8];
                }
#pragma unroll
                for (int mt = 0; mt < 2; ++mt)
#pragma unroll
                    for (int nt = 0; nt < 4; ++nt) {
                        mma16816(acc[mt][nt], aH[mt], bH[nt]);
                        mma16816(acc[mt][nt], aL[mt], bH[nt]);
                        mma16816(acc[mt][nt], aH[mt], bL[nt]);
                    }
            }
        }

        // ---- split-K reduce into stage ----
        __syncthreads();                 // Z consumers done; stage free
        if (kh == 1) {
#pragma unroll
            for (int mt = 0; mt < 2; ++mt)
#pragma unroll
                for (int nt = 0; nt < 4; ++nt) {
                    const int r0 = mh * 32 + mt * 16 + grp;
                    const int n0 = nh * 32 + nt * 8 + qid * 2;
                    stg[r0 * SPAD + n0]       = acc[mt][nt][0];
                    stg[r0 * SPAD + n0 + 1]   = acc[mt][nt][1];
                    stg[(r0+8) * SPAD + n0]   = acc[mt][nt][2];
                    stg[(r0+8) * SPAD + n0+1] = acc[mt][nt][3];
                }
        }
        __syncthreads();
        if (kh == 0) {
#pragma unroll
            for (int mt = 0; mt < 2; ++mt)
#pragma unroll
                for (int nt = 0; nt < 4; ++nt) {
                    const int r0 = mh * 32 + mt * 16 + grp;
                    const int n0 = nh * 32 + nt * 8 + qid * 2;
                    stg[r0 * SPAD + n0]       += acc[mt][nt][0];
                    stg[r0 * SPAD + n0 + 1]   += acc[mt][nt][1];
                    stg[(r0+8) * SPAD + n0]   += acc[mt][nt][2];
                    stg[(r0+8) * SPAD + n0+1] += acc[mt][nt][3];
                }
        }
        __syncthreads();

        // ---- cell update: thread = (batch b, 4 units ug*4..+3) ----
        {
            const int b = tid & 63, ug = tid >> 6;
            float hn[4];
#pragma unroll
            for (int i = 0; i < 4; ++i) {
                const int u = ug * 4 + i, r4 = u * 4;
                float gi = stg[(r4+0) * SPAD + b] + bias[r4+0];
                float gf = stg[(r4+1) * SPAD + b] + bias[r4+1];
                float gg = stg[(r4+2) * SPAD + b] + bias[r4+2];
                float go = stg[(r4+3) * SPAD + b] + bias[r4+3];
                float iv = sigf(gi), fv = sigf(gf), gv = tanhf(gg), ov = sigf(go);
                float cn = fv * csm[u * 64 + b] + iv * gv;
                csm[u * 64 + b] = cn;
                hn[i] = ov * tanhf(cn);
            }
            union { unsigned short s[4]; uint2 v; } ph, pl;
#pragma unroll
            for (int i = 0; i < 4; ++i) split2(hn[i], ph.s[i], pl.s[i]);
            const int B = mb * 64 + b, K = mu * 16 + ug * 4;
            *(uint2*)&g_Zhi[slotW][B][K] = ph.v;
            *(uint2*)&g_Zlo[slotW][B][K] = pl.v;
            float p = 0.f;
#pragma unroll
            for (int i = 0; i < 4; ++i) p += wout[ug * 4 + i] * hn[i];
            pred[ug * 64 + b] = p;
        }
        __syncthreads();
        if (tid < 64)
            g_pout[slotW][mu][mb][tid] =
                pred[tid] + pred[64 + tid] + pred[128 + tid] + pred[192 + tid];
        __threadfence();
        __syncthreads();

        // ---- group barrier (32 CTAs sharing this batch group) ----
        if (tid == 0) {
            atomicAdd((unsigned*)&g_bar[mb], 1u);
            while (g_bar[mb] < barTarget) { }
            __threadfence();
        }
        __syncthreads();
        barTarget += NMU;

        // ---- readout: this CTA finalizes 2 batches ----
        if (tid < 2) {
            const int bl = mu * 2 + tid;
            float s = bout;
#pragma unroll
            for (int m2 = 0; m2 < NMU; ++m2)
                s += __ldcg(&g_pout[slotW][m2][mb][bl]);
            out[(size_t)(mb * 64 + bl) * Tsz + t] = s;
        }
    }
}

extern "C" void kernel_launch(void* const* d_in, const int* in_sizes, int n_in,
                              void* d_out, int out_size)
{
    (void)in_sizes; (void)n_in; (void)out_size;
    cudaFuncSetAttribute(lstm_hmma_kernel, cudaFuncAttributeMaxDynamicSharedMemorySize,
                         SMEM_TOTAL);
    reset_kernel<<<1, 32>>>();
    prep_h0_kernel<<<256, 128>>>((const float*)d_in[2]);
    lstm_hmma_kernel<<<GRIDSZ, BLOCK, SMEM_TOTAL>>>(
        (const float*)d_in[0],  // observation
        (const float*)d_in[1],  // action
        (const float*)d_in[2],  // h0
        (const float*)d_in[3],  // c0
        (const float*)d_in[4],  // W_ih
        (const float*)d_in[5],  // W_hh
        (const float*)d_in[6],  // b_ih
        (const float*)d_in[7],  // b_hh
        (const float*)d_in[8],  // W_out
        (const float*)d_in[9],  // b_out
        (float*)d_out);
}

// round 5
// speedup vs baseline: 3.2733x; 1.3150x over previous
#include <cuda_runtime.h>
#include <cuda_fp16.h>
#include <cstdint>

#define NMU 32
#define NMB 4
#define GRIDSZ 128
#define BLOCK 256
#define Tsz 512
#define Hsz 512

// ---- recurrent kernel smem layout ----
#define WPAD 520
#define ZPAD 40
#define SPAD 68
#define NBLK 16
#define R_OFF_WH   0
#define R_OFF_WL   66560
#define R_OFF_Z    133120      // 2 bufs x 64 x ZPAD fp16
#define R_OFF_ST   143360
#define R_OFF_C    160768
#define R_OFF_WOUT 164864
#define R_OFF_PRED 164928
#define R_SMEM     165952

// ---- prep kernel smem layout ----
#define PWPAD 200
#define PZPAD 40
#define P_OFF_WH 0
#define P_OFF_WL 25600
#define P_OFF_Z  51200         // 256 x PZPAD fp16
#define P_OFF_B  71680
#define P_SMEM   71936

// h ping-pong image (fp16 hi only), [slot][batch][unit]
__device__ unsigned short g_Zh[2][256][512];
// xg[t][mu][row(64)][mb][b(64)] fp32, bias folded  (1 GB static scratch)
__device__ float g_xg[268435456ull];
__device__ float g_pout[2][NMU][NMB][64];
__device__ volatile unsigned g_bar[NMB];

__device__ __forceinline__ void split2h(float v, unsigned short& h, unsigned short& l){
    __half hh = __float2half_rn(v);
    __half ll = __float2half_rn(v - __half2float(hh));
    h = __half_as_ushort(hh); l = __half_as_ushort(ll);
}
__device__ __forceinline__ unsigned short cvt1h(float v){
    return __half_as_ushort(__float2half_rn(v));
}
__device__ __forceinline__ float sigf(float x){ return __fdividef(1.0f, 1.0f + __expf(-x)); }

__device__ __forceinline__ void mma16816(float* d, const unsigned* a, const unsigned* b){
    asm volatile("mma.sync.aligned.m16n8k16.row.col.f32.f16.f16.f32 "
        "{%0,%1,%2,%3}, {%4,%5,%6,%7}, {%8,%9}, {%0,%1,%2,%3};"
        : "+f"(d[0]), "+f"(d[1]), "+f"(d[2]), "+f"(d[3])
        : "r"(a[0]), "r"(a[1]), "r"(a[2]), "r"(a[3]), "r"(b[0]), "r"(b[1]));
}

// ---- init: reset barrier + h0 -> slot-1 fp16 image ----
__global__ void init_kernel(const float* __restrict__ h0){
    if (blockIdx.x == 0 && threadIdx.x < NMB) g_bar[threadIdx.x] = 0u;
    const int b = blockIdx.x;
    const int j = threadIdx.x * 4;
#pragma unroll
    for (int e = 0; e < 4; ++e)
        g_Zh[1][b][j + e] = cvt1h(h0[(size_t)b * Hsz + j + e]);
}

// ---- prep: xg[t][mu][row][mb][b] = W_ih(R) . x(b,t) + b_ih + b_hh ----
// CTA tile: M=64 rows x N=256 (4 timesteps x 64 batches), K=192, fp16 2-term
__global__ void __launch_bounds__(256, 1) prep_xg_kernel(
    const float* __restrict__ obs, const float* __restrict__ act,
    const float* __restrict__ W_ih,
    const float* __restrict__ b_ih, const float* __restrict__ b_hh)
{
    extern __shared__ unsigned char sm8[];
    unsigned short* WH = (unsigned short*)(sm8 + P_OFF_WH);
    unsigned short* WL = (unsigned short*)(sm8 + P_OFF_WL);
    unsigned short* ZH = (unsigned short*)(sm8 + P_OFF_Z);
    float* bias = (float*)(sm8 + P_OFF_B);

    const int tid = threadIdx.x;
    const int wid = tid >> 5, lane = tid & 31, grp = lane >> 2, qid = lane & 3;
    const int tg = blockIdx.x >> 7;
    const int mu = (blockIdx.x >> 2) & 31;
    const int mb = blockIdx.x & 3;
    const int t0 = tg * 4;
    const int mh = wid >> 2;       // M half (32 rows)
    const int nh = wid & 3;        // t within group (64 n each)

    // W_ih rows for this mu (hi/lo fp16)
    {
        const int r = tid >> 2, l4 = tid & 3;
        const int R = (r & 3) * Hsz + mu * 16 + (r >> 2);
        for (int k = l4; k < 192; k += 4) {
            unsigned short h, l; split2h(W_ih[(size_t)R * 192 + k], h, l);
            WH[r * PWPAD + k] = h;
            WL[r * PWPAD + k] = l;
        }
    }
    if (tid < 64) {
        int R = (tid & 3) * Hsz + mu * 16 + (tid >> 2);
        bias[tid] = b_ih[R] + b_hh[R];
    }

    float acc[2][8][4];
#pragma unroll
    for (int mt = 0; mt < 2; ++mt)
#pragma unroll
        for (int nt = 0; nt < 8; ++nt)
#pragma unroll
            for (int j = 0; j < 4; ++j) acc[mt][nt][j] = 0.f;

    // n = tid: tl = n>>6, b = n&63
    const int bg = mb * 64 + (tid & 63);
    const int tt = t0 + (tid >> 6);
    const float* xrow_obs = obs + ((size_t)bg * Tsz + tt) * 128;
    const float* xrow_act = act + ((size_t)bg * Tsz + tt) * 64;

    float4 pf[8];
    {
        const float4* s = (const float4*)xrow_obs;
#pragma unroll
        for (int j = 0; j < 8; ++j) pf[j] = s[j];
    }

    for (int blk = 0; blk < 6; ++blk) {
        __syncthreads();
        // store 32 fp16 (hi only) of this n's k-block
        {
            unsigned short* dst = ZH + tid * PZPAD;
            const float* f = (const float*)pf;
            union { unsigned short s[8]; uint4 v; } u;
#pragma unroll
            for (int g4 = 0; g4 < 4; ++g4) {
#pragma unroll
                for (int j = 0; j < 8; ++j) u.s[j] = cvt1h(f[g4 * 8 + j]);
                *(uint4*)(dst + g4 * 8) = u.v;
            }
        }
        __syncthreads();
        if (blk + 1 < 6) {
            const int nb = blk + 1;
            const float4* s = (nb < 4) ? (const float4*)(xrow_obs + nb * 32)
                                       : (const float4*)(xrow_act + (nb - 4) * 32);
#pragma unroll
            for (int j = 0; j < 8; ++j) pf[j] = s[j];
        }
#pragma unroll
        for (int ks = 0; ks < 2; ++ks) {
            const int kw = blk * 32 + ks * 16 + qid * 2;
            const int kz = ks * 16 + qid * 2;
            unsigned aH[2][4], aL[2][4], bF[8][2];
#pragma unroll
            for (int mt = 0; mt < 2; ++mt) {
                const int r0 = (mh * 32 + mt * 16 + grp) * PWPAD;
                aH[mt][0] = *(const unsigned*)&WH[r0 + kw];
                aH[mt][1] = *(const unsigned*)&WH[r0 + 8 * PWPAD + kw];
                aH[mt][2] = *(const unsigned*)&WH[r0 + kw + 8];
                aH[mt][3] = *(const unsigned*)&WH[r0 + 8 * PWPAD + kw + 8];
                aL[mt][0] = *(const unsigned*)&WL[r0 + kw];
                aL[mt][1] = *(const unsigned*)&WL[r0 + 8 * PWPAD + kw];
                aL[mt][2] = *(const unsigned*)&WL[r0 + kw + 8];
                aL[mt][3] = *(const unsigned*)&WL[r0 + 8 * PWPAD + kw + 8];
            }
#pragma unroll
            for (int nt = 0; nt < 8; ++nt) {
                const int n0 = (nh * 64 + nt * 8 + grp) * PZPAD;
                bF[nt][0] = *(const unsigned*)&ZH[n0 + kz];
                bF[nt][1] = *(const unsigned*)&ZH[n0 + kz + 8];
            }
#pragma unroll
            for (int mt = 0; mt < 2; ++mt)
#pragma unroll
                for (int nt = 0; nt < 8; ++nt) {
                    mma16816(acc[mt][nt], aH[mt], bF[nt]);
                    mma16816(acc[mt][nt], aL[mt], bF[nt]);
                }
        }
    }

    // epilogue: + bias, store to g_xg
    const int tcol = t0 + nh;
    const size_t base = (size_t)(tcol * 32 + mu) * 16384 + (size_t)mb * 64;
#pragma unroll
    for (int mt = 0; mt < 2; ++mt)
#pragma unroll
        for (int nt = 0; nt < 8; ++nt) {
            const int row = mh * 32 + mt * 16 + grp;
            const int bcol = nt * 8 + qid * 2;
            float2 v0 = make_float2(acc[mt][nt][0] + bias[row],
                                    acc[mt][nt][1] + bias[row]);
            float2 v1 = make_float2(acc[mt][nt][2] + bias[row + 8],
                                    acc[mt][nt][3] + bias[row + 8]);
            *(float2*)&g_xg[base + (size_t)row * 256 + bcol] = v0;
            *(float2*)&g_xg[base + (size_t)(row + 8) * 256 + bcol] = v1;
        }
}

// ---- recurrent kernel: gates = xg + h . W_hh^T, K=512, fp16 2-term ----
__global__ void __launch_bounds__(BLOCK, 1) lstm_hmma_kernel(
    const float* __restrict__ c0,
    const float* __restrict__ W_hh,
    const float* __restrict__ W_out, const float* __restrict__ b_out,
    float* __restrict__ out)
{
    extern __shared__ unsigned char sm8[];
    unsigned short* WH = (unsigned short*)(sm8 + R_OFF_WH);
    unsigned short* WL = (unsigned short*)(sm8 + R_OFF_WL);
    unsigned short* Z0 = (unsigned short*)(sm8 + R_OFF_Z);
    float* stg  = (float*)(sm8 + R_OFF_ST);
    float* csm  = (float*)(sm8 + R_OFF_C);
    float* wout = (float*)(sm8 + R_OFF_WOUT);
    float* pred = (float*)(sm8 + R_OFF_PRED);

    const int tid = threadIdx.x;
    const int wid = tid >> 5, lane = tid & 31, grp = lane >> 2, qid = lane & 3;
    const int mu = blockIdx.x >> 2, mb = blockIdx.x & 3;
    const int kh = wid >> 2;            // split-K half
    const int mh = (wid >> 1) & 1;      // M half
    const int nh = wid & 1;             // N half

    // ---- init: W_hh hi/lo, c, wout ----
    {
        const int r = tid >> 2, l4 = tid & 3;
        const int R = (r & 3) * Hsz + mu * 16 + (r >> 2);
        for (int k = l4; k < 512; k += 4) {
            unsigned short h, l; split2h(W_hh[(size_t)R * Hsz + k], h, l);
            WH[r * WPAD + k] = h;
            WL[r * WPAD + k] = l;
        }
    }
    for (int i = tid; i < 16 * 64; i += BLOCK) {
        int u = i >> 6, b = i & 63;
        csm[u * 64 + b] = c0[(size_t)(mb * 64 + b) * Hsz + mu * 16 + u];
    }
    if (tid < 16) wout[tid] = W_out[mu * 16 + tid];
    __syncthreads();

    const float bout = b_out[0];
    unsigned barTarget = NMU;

    const int zn = tid >> 2, zg = tid & 3;
    const int bg = mb * 64 + zn;
    const int eb = tid & 63, ug = tid >> 6;      // epilogue mapping
    const float* xg_my = g_xg + (size_t)mu * 16384 + (size_t)(ug * 16) * 256
                              + (size_t)mb * 64 + eb;

    for (int t = 0; t < Tsz; ++t) {
        const int slotR = (t + 1) & 1, slotW = t & 1;

        float acc[2][4][4];
#pragma unroll
        for (int mt = 0; mt < 2; ++mt)
#pragma unroll
            for (int nt = 0; nt < 4; ++nt)
#pragma unroll
                for (int j = 0; j < 4; ++j) acc[mt][nt][j] = 0.f;

        // prefetch xg for this step into regs (hidden behind the whole mainloop)
        float xgr[16];
        {
            const float* p = xg_my + (size_t)t * 524288;   // t*32*16384
#pragma unroll
            for (int rr = 0; rr < 16; ++rr) xgr[rr] = __ldcg(p + (size_t)rr * 256);
        }

        // software-pipelined Z staging (double buffer, 1 sync/block)
        uint4 R0 = __ldcg((const uint4*)&g_Zh[slotR][bg][zg * 8]);
        *(uint4*)(Z0 + zn * ZPAD + zg * 8) = R0;
        R0 = __ldcg((const uint4*)&g_Zh[slotR][bg][32 + zg * 8]);

        for (int blk = 0; blk < NBLK; ++blk) {
            __syncthreads();
            if (blk + 1 < NBLK)
                *(uint4*)(Z0 + ((blk + 1) & 1) * 64 * ZPAD + zn * ZPAD + zg * 8) = R0;
            if (blk + 2 < NBLK)
                R0 = __ldcg((const uint4*)&g_Zh[slotR][bg][(blk + 2) * 32 + zg * 8]);
            // MMA on buf[blk&1], this warp's 16-k slice
            {
                const unsigned short* ZB = Z0 + (blk & 1) * 64 * ZPAD;
                const int kw = blk * 32 + kh * 16 + qid * 2;
                const int kz = kh * 16 + qid * 2;
                unsigned aH[2][4], aL[2][4], bF[4][2];
#pragma unroll
                for (int mt = 0; mt < 2; ++mt) {
                    const int r0 = (mh * 32 + mt * 16 + grp) * WPAD;
                    aH[mt][0] = *(const unsigned*)&WH[r0 + kw];
                    aH[mt][1] = *(const unsigned*)&WH[r0 + 8 * WPAD + kw];
                    aH[mt][2] = *(const unsigned*)&WH[r0 + kw + 8];
                    aH[mt][3] = *(const unsigned*)&WH[r0 + 8 * WPAD + kw + 8];
                    aL[mt][0] = *(const unsigned*)&WL[r0 + kw];
                    aL[mt][1] = *(const unsigned*)&WL[r0 + 8 * WPAD + kw];
                    aL[mt][2] = *(const unsigned*)&WL[r0 + kw + 8];
                    aL[mt][3] = *(const unsigned*)&WL[r0 + 8 * WPAD + kw + 8];
                }
#pragma unroll
                for (int nt = 0; nt < 4; ++nt) {
                    const int n0 = (nh * 32 + nt * 8 + grp) * ZPAD;
                    bF[nt][0] = *(const unsigned*)&ZB[n0 + kz];
                    bF[nt][1] = *(const unsigned*)&ZB[n0 + kz + 8];
                }
#pragma unroll
                for (int mt = 0; mt < 2; ++mt)
#pragma unroll
                    for (int nt = 0; nt < 4; ++nt) {
                        mma16816(acc[mt][nt], aH[mt], bF[nt]);
                        mma16816(acc[mt][nt], aL[mt], bF[nt]);
                    }
            }
        }

        // ---- split-K reduce ----
        __syncthreads();
        if (kh == 1) {
#pragma unroll
            for (int mt = 0; mt < 2; ++mt)
#pragma unroll
                for (int nt = 0; nt < 4; ++nt) {
                    const int r0 = mh * 32 + mt * 16 + grp;
                    const int n0 = nh * 32 + nt * 8 + qid * 2;
                    stg[r0 * SPAD + n0]         = acc[mt][nt][0];
                    stg[r0 * SPAD + n0 + 1]     = acc[mt][nt][1];
                    stg[(r0+8) * SPAD + n0]     = acc[mt][nt][2];
                    stg[(r0+8) * SPAD + n0 + 1] = acc[mt][nt][3];
                }
        }
        __syncthreads();
        if (kh == 0) {
#pragma unroll
            for (int mt = 0; mt < 2; ++mt)
#pragma unroll
                for (int nt = 0; nt < 4; ++nt) {
                    const int r0 = mh * 32 + mt * 16 + grp;
                    const int n0 = nh * 32 + nt * 8 + qid * 2;
                    stg[r0 * SPAD + n0]         += acc[mt][nt][0];
                    stg[r0 * SPAD + n0 + 1]     += acc[mt][nt][1];
                    stg[(r0+8) * SPAD + n0]     += acc[mt][nt][2];
                    stg[(r0+8) * SPAD + n0 + 1] += acc[mt][nt][3];
                }
        }
        __syncthreads();

        // ---- cell update: thread = (batch eb, units ug*4..+3) ----
        {
            float hn[4];
#pragma unroll
            for (int i = 0; i < 4; ++i) {
                const int u = ug * 4 + i, r4 = u * 4;
                float gi = stg[(r4+0) * SPAD + eb] + xgr[i*4+0];
                float gf = stg[(r4+1) * SPAD + eb] + xgr[i*4+1];
                float gg = stg[(r4+2) * SPAD + eb] + xgr[i*4+2];
                float go = stg[(r4+3) * SPAD + eb] + xgr[i*4+3];
                float iv = sigf(gi), fv = sigf(gf), gv = tanhf(gg), ov = sigf(go);
                float cn = fv * csm[u * 64 + eb] + iv * gv;
                csm[u * 64 + eb] = cn;
                hn[i] = ov * tanhf(cn);
            }
            union { unsigned short s[4]; uint2 v; } ph;
#pragma unroll
            for (int i = 0; i < 4; ++i) ph.s[i] = cvt1h(hn[i]);
            *(uint2*)&g_Zh[slotW][mb * 64 + eb][mu * 16 + ug * 4] = ph.v;
            float p = 0.f;
#pragma unroll
            for (int i = 0; i < 4; ++i) p += wout[ug * 4 + i] * hn[i];
            pred[ug * 64 + eb] = p;
        }
        __syncthreads();
        if (tid < 64)
            g_pout[slotW][mu][mb][tid] =
                pred[tid] + pred[64 + tid] + pred[128 + tid] + pred[192 + tid];
        __threadfence();
        __syncthreads();

        // ---- group barrier (32 CTAs per batch group) ----
        if (tid == 0) {
            atomicAdd((unsigned*)&g_bar[mb], 1u);
            while (g_bar[mb] < barTarget) { }
            __threadfence();
        }
        __syncthreads();
        barTarget += NMU;

        // ---- readout: this CTA finalizes 2 batches ----
        if (tid < 2) {
            const int bl = mu * 2 + tid;
            float s = bout;
#pragma unroll
            for (int m2 = 0; m2 < NMU; ++m2)
                s += __ldcg(&g_pout[slotW][m2][mb][bl]);
            out[(size_t)(mb * 64 + bl) * Tsz + t] = s;
        }
    }
}

extern "C" void kernel_launch(void* const* d_in, const int* in_sizes, int n_in,
                              void* d_out, int out_size)
{
    (void)in_sizes; (void)n_in; (void)out_size;
    cudaFuncSetAttribute(prep_xg_kernel, cudaFuncAttributeMaxDynamicSharedMemorySize, P_SMEM);
    cudaFuncSetAttribute(lstm_hmma_kernel, cudaFuncAttributeMaxDynamicSharedMemorySize, R_SMEM);

    init_kernel<<<256, 128>>>((const float*)d_in[2]);                 // h0 + bar reset
    prep_xg_kernel<<<16384, 256, P_SMEM>>>(
        (const float*)d_in[0],  // observation
        (const float*)d_in[1],  // action
        (const float*)d_in[4],  // W_ih
        (const float*)d_in[6],  // b_ih
        (const float*)d_in[7]); // b_hh
    lstm_hmma_kernel<<<GRIDSZ, BLOCK, R_SMEM>>>(
        (const float*)d_in[3],  // c0
        (const float*)d_in[5],  // W_hh
        (const float*)d_in[8],  // W_out
        (const float*)d_in[9],  // b_out
        (float*)d_out);
}

// round 7
// speedup vs baseline: 3.7156x; 1.1351x over previous
#include <cuda_runtime.h>
#include <cuda_fp16.h>
#include <cstdint>

#define NMU 32
#define NMB 4
#define GRIDSZ 128
#define BLOCK 256
#define Tsz 512
#define Hsz 512

// ---- recurrent kernel smem layout ----
#define WPAD 520
#define ZPAD 40
#define SPAD 68
#define NBLK 16
#define R_OFF_WH   0
#define R_OFF_Z    66560       // 2 bufs x 64 x ZPAD fp16
#define R_OFF_ST   76800
#define R_OFF_C    94208
#define R_OFF_WOUT 98304
#define R_OFF_PRED 98368
#define R_SMEM     99392

// ---- prep kernel smem layout ----
#define PWPAD 200
#define PZPAD 40
#define P_OFF_WH 0
#define P_OFF_WL 25600
#define P_OFF_Z  51200
#define P_OFF_B  71680
#define P_SMEM   71936

// h ping-pong image (fp16), [slot][batch][unit]
__device__ unsigned short g_Zh[2][256][512];
// xg[t][mu][row(64)][mb][b(64)] fp32, bias folded
__device__ float g_xg[268435456ull];
__device__ float g_pout[2][NMU][NMB][64];
__device__ volatile unsigned g_bar[NMB];

__device__ __forceinline__ void split2h(float v, unsigned short& h, unsigned short& l){
    __half hh = __float2half_rn(v);
    __half ll = __float2half_rn(v - __half2float(hh));
    h = __half_as_ushort(hh); l = __half_as_ushort(ll);
}
__device__ __forceinline__ unsigned short cvt1h(float v){
    return __half_as_ushort(__float2half_rn(v));
}
__device__ __forceinline__ float sigf(float x){ return __fdividef(1.0f, 1.0f + __expf(-x)); }

__device__ __forceinline__ void mma16816(float* d, const unsigned* a, const unsigned* b){
    asm volatile("mma.sync.aligned.m16n8k16.row.col.f32.f16.f16.f32 "
        "{%0,%1,%2,%3}, {%4,%5,%6,%7}, {%8,%9}, {%0,%1,%2,%3};"
        : "+f"(d[0]), "+f"(d[1]), "+f"(d[2]), "+f"(d[3])
        : "r"(a[0]), "r"(a[1]), "r"(a[2]), "r"(a[3]), "r"(b[0]), "r"(b[1]));
}
__device__ __forceinline__ void ldsm_x4(unsigned* r, uint32_t addr){
    asm volatile("ldmatrix.sync.aligned.m8n8.x4.shared.b16 {%0,%1,%2,%3}, [%4];"
        : "=r"(r[0]), "=r"(r[1]), "=r"(r[2]), "=r"(r[3]) : "r"(addr));
}
__device__ __forceinline__ uint32_t smem_u32(const void* p){
    uint32_t a; asm("{ .reg .u64 t; cvta.to.shared.u64 t, %1; cvt.u32.u64 %0, t; }" : "=r"(a) : "l"(p));
    return a;
}

// ---- init: reset barrier + h0 -> slot-1 fp16 image ----
__global__ void init_kernel(const float* __restrict__ h0){
    if (blockIdx.x == 0 && threadIdx.x < NMB) g_bar[threadIdx.x] = 0u;
    const int b = blockIdx.x;
    const int j = threadIdx.x * 4;
#pragma unroll
    for (int e = 0; e < 4; ++e)
        g_Zh[1][b][j + e] = cvt1h(h0[(size_t)b * Hsz + j + e]);
}

// ---- prep: xg[t][mu][row][mb][b] = W_ih(R) . x(b,t) + b_ih + b_hh ----
__global__ void __launch_bounds__(256, 1) prep_xg_kernel(
    const float* __restrict__ obs, const float* __restrict__ act,
    const float* __restrict__ W_ih,
    const float* __restrict__ b_ih, const float* __restrict__ b_hh)
{
    extern __shared__ unsigned char sm8[];
    unsigned short* WH = (unsigned short*)(sm8 + P_OFF_WH);
    unsigned short* WL = (unsigned short*)(sm8 + P_OFF_WL);
    unsigned short* ZH = (unsigned short*)(sm8 + P_OFF_Z);
    float* bias = (float*)(sm8 + P_OFF_B);

    const int tid = threadIdx.x;
    const int wid = tid >> 5, lane = tid & 31, grp = lane >> 2, qid = lane & 3;
    const int tg = blockIdx.x >> 7;
    const int mu = (blockIdx.x >> 2) & 31;
    const int mb = blockIdx.x & 3;
    const int t0 = tg * 4;
    const int mh = wid >> 2;
    const int nh = wid & 3;

    {
        const int r = tid >> 2, l4 = tid & 3;
        const int R = (r & 3) * Hsz + mu * 16 + (r >> 2);
        for (int k = l4; k < 192; k += 4) {
            unsigned short h, l; split2h(W_ih[(size_t)R * 192 + k], h, l);
            WH[r * PWPAD + k] = h;
            WL[r * PWPAD + k] = l;
        }
    }
    if (tid < 64) {
        int R = (tid & 3) * Hsz + mu * 16 + (tid >> 2);
        bias[tid] = b_ih[R] + b_hh[R];
    }

    float acc[2][8][4];
#pragma unroll
    for (int mt = 0; mt < 2; ++mt)
#pragma unroll
        for (int nt = 0; nt < 8; ++nt)
#pragma unroll
            for (int j = 0; j < 4; ++j) acc[mt][nt][j] = 0.f;

    const int bg = mb * 64 + (tid & 63);
    const int tt = t0 + (tid >> 6);
    const float* xrow_obs = obs + ((size_t)bg * Tsz + tt) * 128;
    const float* xrow_act = act + ((size_t)bg * Tsz + tt) * 64;

    float4 pf[8];
    {
        const float4* s = (const float4*)xrow_obs;
#pragma unroll
        for (int j = 0; j < 8; ++j) pf[j] = s[j];
    }

    for (int blk = 0; blk < 6; ++blk) {
        __syncthreads();
        {
            unsigned short* dst = ZH + tid * PZPAD;
            const float* f = (const float*)pf;
            union { unsigned short s[8]; uint4 v; } u;
#pragma unroll
            for (int g4 = 0; g4 < 4; ++g4) {
#pragma unroll
                for (int j = 0; j < 8; ++j) u.s[j] = cvt1h(f[g4 * 8 + j]);
                *(uint4*)(dst + g4 * 8) = u.v;
            }
        }
        __syncthreads();
        if (blk + 1 < 6) {
            const int nb = blk + 1;
            const float4* s = (nb < 4) ? (const float4*)(xrow_obs + nb * 32)
                                       : (const float4*)(xrow_act + (nb - 4) * 32);
#pragma unroll
            for (int j = 0; j < 8; ++j) pf[j] = s[j];
        }
#pragma unroll
        for (int ks = 0; ks < 2; ++ks) {
            const int kw = blk * 32 + ks * 16 + qid * 2;
            const int kz = ks * 16 + qid * 2;
            unsigned aH[2][4], aL[2][4], bF[8][2];
#pragma unroll
            for (int mt = 0; mt < 2; ++mt) {
                const int r0 = (mh * 32 + mt * 16 + grp) * PWPAD;
                aH[mt][0] = *(const unsigned*)&WH[r0 + kw];
                aH[mt][1] = *(const unsigned*)&WH[r0 + 8 * PWPAD + kw];
                aH[mt][2] = *(const unsigned*)&WH[r0 + kw + 8];
                aH[mt][3] = *(const unsigned*)&WH[r0 + 8 * PWPAD + kw + 8];
                aL[mt][0] = *(const unsigned*)&WL[r0 + kw];
                aL[mt][1] = *(const unsigned*)&WL[r0 + 8 * PWPAD + kw];
                aL[mt][2] = *(const unsigned*)&WL[r0 + kw + 8];
                aL[mt][3] = *(const unsigned*)&WL[r0 + 8 * PWPAD + kw + 8];
            }
#pragma unroll
            for (int nt = 0; nt < 8; ++nt) {
                const int n0 = (nh * 64 + nt * 8 + grp) * PZPAD;
                bF[nt][0] = *(const unsigned*)&ZH[n0 + kz];
                bF[nt][1] = *(const unsigned*)&ZH[n0 + kz + 8];
            }
#pragma unroll
            for (int mt = 0; mt < 2; ++mt)
#pragma unroll
                for (int nt = 0; nt < 8; ++nt) {
                    mma16816(acc[mt][nt], aH[mt], bF[nt]);
                    mma16816(acc[mt][nt], aL[mt], bF[nt]);
                }
        }
    }

    const int tcol = t0 + nh;
    const size_t base = (size_t)(tcol * 32 + mu) * 16384 + (size_t)mb * 64;
#pragma unroll
    for (int mt = 0; mt < 2; ++mt)
#pragma unroll
        for (int nt = 0; nt < 8; ++nt) {
            const int row = mh * 32 + mt * 16 + grp;
            const int bcol = nt * 8 + qid * 2;
            float2 v0 = make_float2(acc[mt][nt][0] + bias[row],
                                    acc[mt][nt][1] + bias[row]);
            float2 v1 = make_float2(acc[mt][nt][2] + bias[row + 8],
                                    acc[mt][nt][3] + bias[row + 8]);
            *(float2*)&g_xg[base + (size_t)row * 256 + bcol] = v0;
            *(float2*)&g_xg[base + (size_t)(row + 8) * 256 + bcol] = v1;
        }
}

// ---- recurrent: gates = xg + h . W_hh^T, K=512, single-fp16, ldmatrix ----
__global__ void __launch_bounds__(BLOCK, 1) lstm_hmma_kernel(
    const float* __restrict__ c0,
    const float* __restrict__ W_hh,
    const float* __restrict__ W_out, const float* __restrict__ b_out,
    float* __restrict__ out)
{
    extern __shared__ unsigned char sm8[];
    unsigned short* WH = (unsigned short*)(sm8 + R_OFF_WH);
    unsigned short* Z0 = (unsigned short*)(sm8 + R_OFF_Z);
    float* stg  = (float*)(sm8 + R_OFF_ST);
    float* csm  = (float*)(sm8 + R_OFF_C);
    float* wout = (float*)(sm8 + R_OFF_WOUT);
    float* pred = (float*)(sm8 + R_OFF_PRED);

    const int tid = threadIdx.x;
    const int wid = tid >> 5, lane = tid & 31, grp = lane >> 2, qid = lane & 3;
    const int mu = blockIdx.x >> 2, mb = blockIdx.x & 3;
    const int mh = wid >> 2;            // M half (32 rows)
    const int nq = wid & 3;             // N quarter (16 cols)

    // ---- init: W_hh (fp16 hi only), c, wout ----
    {
        const int r = tid >> 2, l4 = tid & 3;
        const int R = (r & 3) * Hsz + mu * 16 + (r >> 2);
        for (int k = l4; k < 512; k += 4)
            WH[r * WPAD + k] = cvt1h(W_hh[(size_t)R * Hsz + k]);
    }
    for (int i = tid; i < 16 * 64; i += BLOCK) {
        int u = i >> 6, b = i & 63;
        csm[u * 64 + b] = c0[(size_t)(mb * 64 + b) * Hsz + mu * 16 + u];
    }
    if (tid < 16) wout[tid] = W_out[mu * 16 + tid];
    __syncthreads();

    const float bout = b_out[0];
    unsigned barTarget = NMU;

    // ldmatrix per-lane addresses
    const int lrow = lane & 7, lgrp = lane >> 3;
    uint32_t aAddr[2];
#pragma unroll
    for (int mt = 0; mt < 2; ++mt) {
        const int row = mh * 32 + mt * 16 + (lgrp & 1) * 8 + lrow;
        aAddr[mt] = smem_u32(WH) + (uint32_t)(row * WPAD + (lgrp >> 1) * 8) * 2;
    }
    const uint32_t bAddr = smem_u32(Z0)
        + (uint32_t)((nq * 16 + (lgrp >> 1) * 8 + lrow) * ZPAD + (lgrp & 1) * 8) * 2;

    const int zn = tid >> 2, zg = tid & 3;
    const int bg = mb * 64 + zn;
    const int eb = tid & 63, ug = tid >> 6;
    const float* xg_my = g_xg + (size_t)mu * 16384 + (size_t)(ug * 16) * 256
                              + (size_t)mb * 64 + eb;

    for (int t = 0; t < Tsz; ++t) {
        const int slotR = (t + 1) & 1, slotW = t & 1;

        float acc[2][2][4];
#pragma unroll
        for (int mt = 0; mt < 2; ++mt)
#pragma unroll
            for (int nt = 0; nt < 2; ++nt)
#pragma unroll
                for (int j = 0; j < 4; ++j) acc[mt][nt][j] = 0.f;

        float xgr[16];
        {
            const float* p = xg_my + (size_t)t * 524288;
#pragma unroll
            for (int rr = 0; rr < 16; ++rr) xgr[rr] = __ldcg(p + (size_t)rr * 256);
        }

        uint4 R0 = __ldcg((const uint4*)&g_Zh[slotR][bg][zg * 8]);
        *(uint4*)(Z0 + zn * ZPAD + zg * 8) = R0;
        R0 = __ldcg((const uint4*)&g_Zh[slotR][bg][32 + zg * 8]);

        for (int blk = 0; blk < NBLK; ++blk) {
            __syncthreads();
            if (blk + 1 < NBLK)
                *(uint4*)(Z0 + ((blk + 1) & 1) * 64 * ZPAD + zn * ZPAD + zg * 8) = R0;
            if (blk + 2 < NBLK)
                R0 = __ldcg((const uint4*)&g_Zh[slotR][bg][(blk + 2) * 32 + zg * 8]);
            {
                const uint32_t bufo = (uint32_t)((blk & 1) * 64 * ZPAD * 2);
#pragma unroll
                for (int ks = 0; ks < 2; ++ks) {
                    const uint32_t ko = (uint32_t)((blk * 32 + ks * 16) * 2);
                    unsigned A0[4], A1[4], Bv[4];
                    ldsm_x4(A0, aAddr[0] + ko);
                    ldsm_x4(A1, aAddr[1] + ko);
                    ldsm_x4(Bv, bAddr + bufo + (uint32_t)(ks * 32));
                    mma16816(acc[0][0], A0, Bv);
                    mma16816(acc[0][1], A0, Bv + 2);
                    mma16816(acc[1][0], A1, Bv);
                    mma16816(acc[1][1], A1, Bv + 2);
                }
            }
        }

        // ---- write gates to stage (no split-K) ----
        __syncthreads();
#pragma unroll
        for (int mt = 0; mt < 2; ++mt)
#pragma unroll
            for (int nt = 0; nt < 2; ++nt) {
                const int r0 = mh * 32 + mt * 16 + grp;
                const int n0 = nq * 16 + nt * 8 + qid * 2;
                stg[r0 * SPAD + n0]         = acc[mt][nt][0];
                stg[r0 * SPAD + n0 + 1]     = acc[mt][nt][1];
                stg[(r0+8) * SPAD + n0]     = acc[mt][nt][2];
                stg[(r0+8) * SPAD + n0 + 1] = acc[mt][nt][3];
            }
        __syncthreads();

        // ---- cell update: thread = (batch eb, units ug*4..+3) ----
        {
            float hn[4];
#pragma unroll
            for (int i = 0; i < 4; ++i) {
                const int u = ug * 4 + i, r4 = u * 4;
                float gi = stg[(r4+0) * SPAD + eb] + xgr[i*4+0];
                float gf = stg[(r4+1) * SPAD + eb] + xgr[i*4+1];
                float gg = stg[(r4+2) * SPAD + eb] + xgr[i*4+2];
                float go = stg[(r4+3) * SPAD + eb] + xgr[i*4+3];
                float iv = sigf(gi), fv = sigf(gf), gv = tanhf(gg), ov = sigf(go);
                float cn = fv * csm[u * 64 + eb] + iv * gv;
                csm[u * 64 + eb] = cn;
                hn[i] = ov * tanhf(cn);
            }
            union { unsigned short s[4]; uint2 v; } ph;
#pragma unroll
            for (int i = 0; i < 4; ++i) ph.s[i] = cvt1h(hn[i]);
            *(uint2*)&g_Zh[slotW][mb * 64 + eb][mu * 16 + ug * 4] = ph.v;
            float p = 0.f;
#pragma unroll
            for (int i = 0; i < 4; ++i) p += wout[ug * 4 + i] * hn[i];
            pred[ug * 64 + eb] = p;
        }
        __syncthreads();
        if (tid < 64)
            g_pout[slotW][mu][mb][tid] =
                pred[tid] + pred[64 + tid] + pred[128 + tid] + pred[192 + tid];
        __threadfence();
        __syncthreads();

        // ---- group barrier (32 CTAs per batch group) ----
        if (tid == 0) {
            atomicAdd((unsigned*)&g_bar[mb], 1u);
            while (g_bar[mb] < barTarget) { }
            __threadfence();
        }
        __syncthreads();
        barTarget += NMU;

        // ---- readout: this CTA finalizes 2 batches ----
        if (tid < 2) {
            const int bl = mu * 2 + tid;
            float s = bout;
#pragma unroll
            for (int m2 = 0; m2 < NMU; ++m2)
                s += __ldcg(&g_pout[slotW][m2][mb][bl]);
            out[(size_t)(mb * 64 + bl) * Tsz + t] = s;
        }
    }
}

extern "C" void kernel_launch(void* const* d_in, const int* in_sizes, int n_in,
                              void* d_out, int out_size)
{
    (void)in_sizes; (void)n_in; (void)out_size;
    cudaFuncSetAttribute(prep_xg_kernel, cudaFuncAttributeMaxDynamicSharedMemorySize, P_SMEM);
    cudaFuncSetAttribute(lstm_hmma_kernel, cudaFuncAttributeMaxDynamicSharedMemorySize, R_SMEM);

    init_kernel<<<256, 128>>>((const float*)d_in[2]);
    prep_xg_kernel<<<16384, 256, P_SMEM>>>(
        (const float*)d_in[0],  // observation
        (const float*)d_in[1],  // action
        (const float*)d_in[4],  // W_ih
        (const float*)d_in[6],  // b_ih
        (const float*)d_in[7]); // b_hh
    lstm_hmma_kernel<<<GRIDSZ, BLOCK, R_SMEM>>>(
        (const float*)d_in[3],  // c0
        (const float*)d_in[5],  // W_hh
        (const float*)d_in[8],  // W_out
        (const float*)d_in[9],  // b_out
        (float*)d_out);
}

// round 9
// speedup vs baseline: 3.8696x; 1.0415x over previous
#include <cuda_runtime.h>
#include <cuda_fp16.h>
#include <cstdint>

#define NMU 32
#define NMB 4
#define GRIDSZ 128
#define BLOCK 256
#define Tsz 512
#define Hsz 512

// ---- recurrent kernel smem layout ----
#define WPAD 520
#define ZPAD 520
#define SPAD 68
#define R_OFF_WH   0
#define R_OFF_Z    66560
#define R_OFF_ST   133120
#define R_OFF_C    150528
#define R_OFF_WOUT 154624
#define R_OFF_PRED 154688
#define R_SMEM     155712

// ---- prep kernel smem layout ----
#define PWPAD 200
#define PZPAD 40
#define P_OFF_WH 0
#define P_OFF_WL 25600
#define P_OFF_Z  51200
#define P_OFF_B  71680
#define P_SMEM   71936

// h ping-pong image (fp16), [slot][batch][unit]
__device__ unsigned short g_Zh[2][256][512];
// xg[t][mu][row(64)][mb][b(64)] fp32, bias folded
__device__ float g_xg[268435456ull];
__device__ float g_pout[2][NMU][NMB][64];
__device__ volatile unsigned g_bar[NMB];

__device__ __forceinline__ void split2h(float v, unsigned short& h, unsigned short& l){
    __half hh = __float2half_rn(v);
    __half ll = __float2half_rn(v - __half2float(hh));
    h = __half_as_ushort(hh); l = __half_as_ushort(ll);
}
__device__ __forceinline__ unsigned short cvt1h(float v){
    return __half_as_ushort(__float2half_rn(v));
}
__device__ __forceinline__ float sigf(float x){ return __fdividef(1.0f, 1.0f + __expf(-x)); }

__device__ __forceinline__ void mma16816(float* d, const unsigned* a, const unsigned* b){
    asm volatile("mma.sync.aligned.m16n8k16.row.col.f32.f16.f16.f32 "
        "{%0,%1,%2,%3}, {%4,%5,%6,%7}, {%8,%9}, {%0,%1,%2,%3};"
        : "+f"(d[0]), "+f"(d[1]), "+f"(d[2]), "+f"(d[3])
        : "r"(a[0]), "r"(a[1]), "r"(a[2]), "r"(a[3]), "r"(b[0]), "r"(b[1]));
}
__device__ __forceinline__ void ldsm_x4(unsigned* r, uint32_t addr){
    asm volatile("ldmatrix.sync.aligned.m8n8.x4.shared.b16 {%0,%1,%2,%3}, [%4];"
        : "=r"(r[0]), "=r"(r[1]), "=r"(r[2]), "=r"(r[3]) : "r"(addr));
}
__device__ __forceinline__ uint32_t smem_u32(const void* p){
    uint32_t a; asm("{ .reg .u64 t; cvta.to.shared.u64 t, %1; cvt.u32.u64 %0, t; }" : "=r"(a) : "l"(p));
    return a;
}
__device__ __forceinline__ void cp_async16(uint32_t dst, const void* src){
    asm volatile("cp.async.cg.shared.global [%0], [%1], 16;" :: "r"(dst), "l"(src));
}
__device__ __forceinline__ void cp_commit_wait(){
    asm volatile("cp.async.commit_group;\ncp.async.wait_group 0;" ::: "memory");
}

// ---- init: reset barrier + h0 -> slot-1 fp16 image ----
__global__ void init_kernel(const float* __restrict__ h0){
    if (blockIdx.x == 0 && threadIdx.x < NMB) g_bar[threadIdx.x] = 0u;
    const int b = blockIdx.x;
    const int j = threadIdx.x * 4;
#pragma unroll
    for (int e = 0; e < 4; ++e)
        g_Zh[1][b][j + e] = cvt1h(h0[(size_t)b * Hsz + j + e]);
}

// ---- prep: xg[t][mu][row][mb][b] = W_ih(R) . x(b,t) + b_ih + b_hh ----
// CTA: M=64 rows x N=256 (4 t x 64 b), K=192; inner loop over 4 t-groups (16 t total)
__global__ void __launch_bounds__(256, 1) prep_xg_kernel(
    const float* __restrict__ obs, const float* __restrict__ act,
    const float* __restrict__ W_ih,
    const float* __restrict__ b_ih, const float* __restrict__ b_hh)
{
    extern __shared__ unsigned char sm8[];
    unsigned short* WH = (unsigned short*)(sm8 + P_OFF_WH);
    unsigned short* WL = (unsigned short*)(sm8 + P_OFF_WL);
    unsigned short* ZH = (unsigned short*)(sm8 + P_OFF_Z);
    float* bias = (float*)(sm8 + P_OFF_B);

    const int tid = threadIdx.x;
    const int wid = tid >> 5, lane = tid & 31, grp = lane >> 2, qid = lane & 3;
    const int tgB = blockIdx.x >> 7;
    const int mu = (blockIdx.x >> 2) & 31;
    const int mb = blockIdx.x & 3;
    const int mh = wid >> 2;
    const int nh = wid & 3;

    {
        const int r = tid >> 2, l4 = tid & 3;
        const int R = (r & 3) * Hsz + mu * 16 + (r >> 2);
        for (int k = l4; k < 192; k += 4) {
            unsigned short h, l; split2h(W_ih[(size_t)R * 192 + k], h, l);
            WH[r * PWPAD + k] = h;
            WL[r * PWPAD + k] = l;
        }
    }
    if (tid < 64) {
        int R = (tid & 3) * Hsz + mu * 16 + (tid >> 2);
        bias[tid] = b_ih[R] + b_hh[R];
    }
    __syncthreads();

    const int bg = mb * 64 + (tid & 63);

    for (int tg = 0; tg < 4; ++tg) {
        const int t0 = tgB * 16 + tg * 4;
        const int tt = t0 + (tid >> 6);
        const float* xrow_obs = obs + ((size_t)bg * Tsz + tt) * 128;
        const float* xrow_act = act + ((size_t)bg * Tsz + tt) * 64;

        float acc[2][8][4];
#pragma unroll
        for (int mt = 0; mt < 2; ++mt)
#pragma unroll
            for (int nt = 0; nt < 8; ++nt)
#pragma unroll
                for (int j = 0; j < 4; ++j) acc[mt][nt][j] = 0.f;

        float4 pf[8];
        {
            const float4* s = (const float4*)xrow_obs;
#pragma unroll
            for (int j = 0; j < 8; ++j) pf[j] = s[j];
        }

        for (int blk = 0; blk < 6; ++blk) {
            __syncthreads();
            {
                unsigned short* dst = ZH + tid * PZPAD;
                const float* f = (const float*)pf;
                union { unsigned short s[8]; uint4 v; } u;
#pragma unroll
                for (int g4 = 0; g4 < 4; ++g4) {
#pragma unroll
                    for (int j = 0; j < 8; ++j) u.s[j] = cvt1h(f[g4 * 8 + j]);
                    *(uint4*)(dst + g4 * 8) = u.v;
                }
            }
            __syncthreads();
            if (blk + 1 < 6) {
                const int nb = blk + 1;
                const float4* s = (nb < 4) ? (const float4*)(xrow_obs + nb * 32)
                                           : (const float4*)(xrow_act + (nb - 4) * 32);
#pragma unroll
                for (int j = 0; j < 8; ++j) pf[j] = s[j];
            }
#pragma unroll
            for (int ks = 0; ks < 2; ++ks) {
                const int kw = blk * 32 + ks * 16 + qid * 2;
                const int kz = ks * 16 + qid * 2;
                unsigned aH[2][4], aL[2][4], bF[8][2];
#pragma unroll
                for (int mt = 0; mt < 2; ++mt) {
                    const int r0 = (mh * 32 + mt * 16 + grp) * PWPAD;
                    aH[mt][0] = *(const unsigned*)&WH[r0 + kw];
                    aH[mt][1] = *(const unsigned*)&WH[r0 + 8 * PWPAD + kw];
                    aH[mt][2] = *(const unsigned*)&WH[r0 + kw + 8];
                    aH[mt][3] = *(const unsigned*)&WH[r0 + 8 * PWPAD + kw + 8];
                    aL[mt][0] = *(const unsigned*)&WL[r0 + kw];
                    aL[mt][1] = *(const unsigned*)&WL[r0 + 8 * PWPAD + kw];
                    aL[mt][2] = *(const unsigned*)&WL[r0 + kw + 8];
                    aL[mt][3] = *(const unsigned*)&WL[r0 + 8 * PWPAD + kw + 8];
                }
#pragma unroll
                for (int nt = 0; nt < 8; ++nt) {
                    const int n0 = (nh * 64 + nt * 8 + grp) * PZPAD;
                    bF[nt][0] = *(const unsigned*)&ZH[n0 + kz];
                    bF[nt][1] = *(const unsigned*)&ZH[n0 + kz + 8];
                }
#pragma unroll
                for (int mt = 0; mt < 2; ++mt)
#pragma unroll
                    for (int nt = 0; nt < 8; ++nt) {
                        mma16816(acc[mt][nt], aH[mt], bF[nt]);
                        mma16816(acc[mt][nt], aL[mt], bF[nt]);
                    }
            }
        }

        const int tcol = t0 + nh;
        const size_t base = (size_t)(tcol * 32 + mu) * 16384 + (size_t)mb * 64;
#pragma unroll
        for (int mt = 0; mt < 2; ++mt)
#pragma unroll
            for (int nt = 0; nt < 8; ++nt) {
                const int row = mh * 32 + mt * 16 + grp;
                const int bcol = nt * 8 + qid * 2;
                float2 v0 = make_float2(acc[mt][nt][0] + bias[row],
                                        acc[mt][nt][1] + bias[row]);
                float2 v1 = make_float2(acc[mt][nt][2] + bias[row + 8],
                                        acc[mt][nt][3] + bias[row + 8]);
                *(float2*)&g_xg[base + (size_t)row * 256 + bcol] = v0;
                *(float2*)&g_xg[base + (size_t)(row + 8) * 256 + bcol] = v1;
            }
        __syncthreads();
    }
}

// ---- recurrent: gates = xg + h . W_hh^T, K=512, one-shot Z staging ----
__global__ void __launch_bounds__(BLOCK, 1) lstm_hmma_kernel(
    const float* __restrict__ c0,
    const float* __restrict__ W_hh,
    const float* __restrict__ W_out, const float* __restrict__ b_out,
    float* __restrict__ out)
{
    extern __shared__ unsigned char sm8[];
    unsigned short* WH = (unsigned short*)(sm8 + R_OFF_WH);
    unsigned short* Z0 = (unsigned short*)(sm8 + R_OFF_Z);
    float* stg  = (float*)(sm8 + R_OFF_ST);
    float* csm  = (float*)(sm8 + R_OFF_C);
    float* wout = (float*)(sm8 + R_OFF_WOUT);
    float* pred = (float*)(sm8 + R_OFF_PRED);

    const int tid = threadIdx.x;
    const int wid = tid >> 5, lane = tid & 31, grp = lane >> 2, qid = lane & 3;
    const int mu = blockIdx.x >> 2, mb = blockIdx.x & 3;
    const int mh = wid >> 2;            // M half (32 rows)
    const int nq = wid & 3;             // N quarter (16 cols)

    // ---- init: W_hh (fp16), c, wout ----
    {
        const int r = tid >> 2, l4 = tid & 3;
        const int R = (r & 3) * Hsz + mu * 16 + (r >> 2);
        for (int k = l4; k < 512; k += 4)
            WH[r * WPAD + k] = cvt1h(W_hh[(size_t)R * Hsz + k]);
    }
    for (int i = tid; i < 16 * 64; i += BLOCK) {
        int u = i >> 6, b = i & 63;
        csm[u * 64 + b] = c0[(size_t)(mb * 64 + b) * Hsz + mu * 16 + u];
    }
    if (tid < 16) wout[tid] = W_out[mu * 16 + tid];
    __syncthreads();

    const float bout = b_out[0];
    unsigned barTarget = NMU;

    // ldmatrix per-lane addresses
    const int lrow = lane & 7, lgrp = lane >> 3;
    uint32_t aAddr[2];
#pragma unroll
    for (int mt = 0; mt < 2; ++mt) {
        const int row = mh * 32 + mt * 16 + (lgrp & 1) * 8 + lrow;
        aAddr[mt] = smem_u32(WH) + (uint32_t)(row * WPAD + (lgrp >> 1) * 8) * 2;
    }
    const uint32_t bAddr = smem_u32(Z0)
        + (uint32_t)((nq * 16 + (lgrp >> 1) * 8 + lrow) * ZPAD + (lgrp & 1) * 8) * 2;

    // staging mapping: row = tid&63, chunk q = tid>>6, granules q+4j (j=0..15)
    const int zr = tid & 63, zq = tid >> 6;
    const int bg = mb * 64 + zr;
    const uint32_t zdst = smem_u32(Z0) + (uint32_t)(zr * ZPAD) * 2;

    const int eb = tid & 63, ug = tid >> 6;
    const float* xg_my = g_xg + (size_t)mu * 16384 + (size_t)(ug * 16) * 256
                              + (size_t)mb * 64 + eb;

    for (int t = 0; t < Tsz; ++t) {
        const int slotR = (t + 1) & 1, slotW = t & 1;

        // ---- one-shot Z staging via cp.async (64KB, conflict-free) ----
        {
            const unsigned short* srow = &g_Zh[slotR][bg][0];
#pragma unroll
            for (int j = 0; j < 16; ++j) {
                const int g = zq + 4 * j;
                cp_async16(zdst + (uint32_t)(g * 16), srow + g * 8);
            }
        }
        // xg prefetch (independent of Z)
        float xgr[16];
        {
            const float* p = xg_my + (size_t)t * 524288;
#pragma unroll
            for (int rr = 0; rr < 16; ++rr) xgr[rr] = __ldcg(p + (size_t)rr * 256);
        }
        cp_commit_wait();
        __syncthreads();

        // ---- zero-sync MMA mainloop: 32 k-slices ----
        float acc[2][2][4];
#pragma unroll
        for (int mt = 0; mt < 2; ++mt)
#pragma unroll
            for (int nt = 0; nt < 2; ++nt)
#pragma unroll
                for (int j = 0; j < 4; ++j) acc[mt][nt][j] = 0.f;

#pragma unroll
        for (int sl = 0; sl < 32; ++sl) {
            const uint32_t ko = (uint32_t)(sl * 16 * 2);
            unsigned A0[4], A1[4], Bv[4];
            ldsm_x4(A0, aAddr[0] + ko);
            ldsm_x4(A1, aAddr[1] + ko);
            ldsm_x4(Bv, bAddr + ko);
            mma16816(acc[0][0], A0, Bv);
            mma16816(acc[0][1], A0, Bv + 2);
            mma16816(acc[1][0], A1, Bv);
            mma16816(acc[1][1], A1, Bv + 2);
        }

        // ---- gates to stage ----
        __syncthreads();
#pragma unroll
        for (int mt = 0; mt < 2; ++mt)
#pragma unroll
            for (int nt = 0; nt < 2; ++nt) {
                const int r0 = mh * 32 + mt * 16 + grp;
                const int n0 = nq * 16 + nt * 8 + qid * 2;
                stg[r0 * SPAD + n0]         = acc[mt][nt][0];
                stg[r0 * SPAD + n0 + 1]     = acc[mt][nt][1];
                stg[(r0+8) * SPAD + n0]     = acc[mt][nt][2];
                stg[(r0+8) * SPAD + n0 + 1] = acc[mt][nt][3];
            }
        __syncthreads();

        // ---- cell update: thread = (batch eb, units ug*4..+3) ----
        {
            float hn[4];
#pragma unroll
            for (int i = 0; i < 4; ++i) {
                const int u = ug * 4 + i, r4 = u * 4;
                float gi = stg[(r4+0) * SPAD + eb] + xgr[i*4+0];
                float gf = stg[(r4+1) * SPAD + eb] + xgr[i*4+1];
                float gg = stg[(r4+2) * SPAD + eb] + xgr[i*4+2];
                float go = stg[(r4+3) * SPAD + eb] + xgr[i*4+3];
                float iv = sigf(gi), fv = sigf(gf), gv = tanhf(gg), ov = sigf(go);
                float cn = fv * csm[u * 64 + eb] + iv * gv;
                csm[u * 64 + eb] = cn;
                hn[i] = ov * tanhf(cn);
            }
            union { unsigned short s[4]; uint2 v; } ph;
#pragma unroll
            for (int i = 0; i < 4; ++i) ph.s[i] = cvt1h(hn[i]);
            *(uint2*)&g_Zh[slotW][mb * 64 + eb][mu * 16 + ug * 4] = ph.v;
            float p = 0.f;
#pragma unroll
            for (int i = 0; i < 4; ++i) p += wout[ug * 4 + i] * hn[i];
            pred[ug * 64 + eb] = p;
        }
        __syncthreads();
        if (tid < 64)
            g_pout[slotW][mu][mb][tid] =
                pred[tid] + pred[64 + tid] + pred[128 + tid] + pred[192 + tid];
        __threadfence();
        __syncthreads();

        // ---- group barrier (32 CTAs per batch group) ----
        if (tid == 0) {
            atomicAdd((unsigned*)&g_bar[mb], 1u);
            while (g_bar[mb] < barTarget) { }
            __threadfence();
        }
        __syncthreads();
        barTarget += NMU;

        // ---- readout: this CTA finalizes 2 batches ----
        if (tid < 2) {
            const int bl = mu * 2 + tid;
            float s = bout;
#pragma unroll
            for (int m2 = 0; m2 < NMU; ++m2)
                s += __ldcg(&g_pout[slotW][m2][mb][bl]);
            out[(size_t)(mb * 64 + bl) * Tsz + t] = s;
        }
    }
}

extern "C" void kernel_launch(void* const* d_in, const int* in_sizes, int n_in,
                              void* d_out, int out_size)
{
    (void)in_sizes; (void)n_in; (void)out_size;
    cudaFuncSetAttribute(prep_xg_kernel, cudaFuncAttributeMaxDynamicSharedMemorySize, P_SMEM);
    cudaFuncSetAttribute(lstm_hmma_kernel, cudaFuncAttributeMaxDynamicSharedMemorySize, R_SMEM);

    init_kernel<<<256, 128>>>((const float*)d_in[2]);
    prep_xg_kernel<<<4096, 256, P_SMEM>>>(
        (const float*)d_in[0],  // observation
        (const float*)d_in[1],  // action
        (const float*)d_in[4],  // W_ih
        (const float*)d_in[6],  // b_ih
        (const float*)d_in[7]); // b_hh
    lstm_hmma_kernel<<<GRIDSZ, BLOCK, R_SMEM>>>(
        (const float*)d_in[3],  // c0
        (const float*)d_in[5],  // W_hh
        (const float*)d_in[8],  // W_out
        (const float*)d_in[9],  // b_out
        (float*)d_out);
}